// round 17
// baseline (speedup 1.0000x reference)
#include <cuda_runtime.h>
#include <cuda_bf16.h>
#include <cstdint>
#include <stdint.h>
#include <math.h>

#define B_  128
#define C_  2048
#define HW_ 121
#define M_  (B_*HW_)   /* 15488 */

// Static device scratch (no runtime allocation).
// x_filt bf16 COL-major: element (m, c) at c*M_ + m  (i.e. [c][m], m contiguous)
__device__ __align__(1024) __nv_bfloat16 g_xfb[31719424];
__device__ __align__(1024) __nv_bfloat16 g_wb[4194304];   // W bf16 [o][c], c contiguous

__device__ __forceinline__ uint32_t smem_addr_u32(const void* p) {
    uint32_t a;
    asm("{ .reg .u64 t; cvta.to.shared.u64 t, %1; cvt.u32.u64 %0, t; }" : "=r"(a) : "l"(p));
    return a;
}
__device__ __forceinline__ void cpa16(uint32_t s, const void* g) {
    asm volatile("cp.async.cg.shared.global [%0], [%1], 16;" :: "r"(s), "l"(g));
}
__device__ __forceinline__ void ldsm4(uint32_t* r, uint32_t addr) {
    asm volatile("ldmatrix.sync.aligned.m8n8.x4.shared.b16 {%0,%1,%2,%3}, [%4];"
                 : "=r"(r[0]), "=r"(r[1]), "=r"(r[2]), "=r"(r[3]) : "r"(addr));
}
__device__ __forceinline__ void ldsm4t(uint32_t* r, uint32_t addr) {
    asm volatile("ldmatrix.sync.aligned.m8n8.x4.trans.shared.b16 {%0,%1,%2,%3}, [%4];"
                 : "=r"(r[0]), "=r"(r[1]), "=r"(r[2]), "=r"(r[3]) : "r"(addr));
}
__device__ __forceinline__ void mma16816(float* d, const uint32_t* a, uint32_t b0, uint32_t b1) {
    asm volatile(
        "mma.sync.aligned.m16n8k16.row.col.f32.bf16.bf16.f32 "
        "{%0,%1,%2,%3}, {%4,%5,%6,%7}, {%8,%9}, {%0,%1,%2,%3};"
        : "+f"(d[0]), "+f"(d[1]), "+f"(d[2]), "+f"(d[3])
        : "r"(a[0]), "r"(a[1]), "r"(a[2]), "r"(a[3]), "r"(b0), "r"(b1));
}

// ---------------------------------------------------------------------------
// K2': fused taps + spatial filter via bf16 mma, one block per channel.
// Warp-specialized: warps 0-3 stream X (gmem->smem bf16) while warps 4-7
// compute Mu -> taps -> T tile. Sub-block phases use bar.sync 1,128.
// Header region 2048B (ct 64B + Mu 512B + ks 512B) — tiles start at +2048.
// ---------------------------------------------------------------------------
__global__ __launch_bounds__(256, 3)
void filter_mma2(const float* __restrict__ x, const float* __restrict__ ft) {
    extern __shared__ char smf[];
    float* ct = reinterpret_cast<float*>(smf);        // 16 (11 used)
    float* Mu = ct + 16;                              // 128 (121 used)
    float* ks = Mu + 128;                             // 128 (121 used)
    char*  base = smf + 2048;                         // T: 32KB, X: 32KB
    uint32_t sb = smem_addr_u32(base);
    uint32_t Tb = sb, Xb = sb + 32768;

    int c = blockIdx.x;
    int tid = threadIdx.x, wid = tid >> 5, lane = tid & 31;

    if (wid >= 4) {
        // --- consumer half: taps + T tile ---
        int wg = tid - 128;
        if (wg < 11) ct[wg] = cospif(2.0f * (float)wg / 11.0f);
        if (wg < 121) {
            float cutoff = fminf(fmaxf(ft[c], 0.05f), 0.5f);
            int u = wg / 11, v = wg - u * 11;
            int a = (u + 5) % 11, b = (v + 5) % 11;
            float dy = (float)(a - 5), dx = (float)(b - 5);
            float dn = sqrtf(dy*dy + dx*dx) / (sqrtf(50.0f) + 1e-6f);
            Mu[wg] = 1.0f / (1.0f + expf(-10.0f * (dn - cutoff)));
        }
        asm volatile("bar.sync 1, 128;" ::: "memory");
        if (wg < 121) {
            int h = wg / 11, w = wg - (wg / 11) * 11;
            float acc = 0.0f;
            int ru = 0;
            #pragma unroll 1
            for (int u = 0; u < 11; u++) {
                const float* mrow = &Mu[u * 11];
                int ph = ru;
                #pragma unroll
                for (int v = 0; v < 11; v++) {
                    acc += mrow[v] * ct[ph];
                    ph += w; if (ph >= 11) ph -= 11;
                }
                ru += h; if (ru >= 11) ru -= 11;
            }
            ks[wg] = acc * (1.0f / 121.0f);
        }
        asm volatile("bar.sync 1, 128;" ::: "memory");
        // build T (o rows x i cols, bf16, swizzled 256B rows)
        for (int idx = wg; idx < 16384; idx += 128) {
            int o = idx >> 7, i = idx & 127;
            float v = 0.0f;
            if (o < 121 && i < 121) {
                int ho = o / 11, wo = o - ho*11;
                int hi = i / 11, wi = i - hi*11;
                int dh = ho - hi; if (dh < 0) dh += 11;
                int dw = wo - wi; if (dw < 0) dw += 11;
                v = ks[dh*11 + dw];
            }
            uint32_t off = (uint32_t)o*256 + ((((uint32_t)i >> 3) ^ (o & 7)) << 4) + (i & 7)*2;
            *reinterpret_cast<__nv_bfloat16*>(base + off) = __float2bfloat16_rn(v);
        }
    } else {
        // --- producer half: stream X (b rows x i cols) ---
        const float* xc = x + (size_t)c * HW_;
        for (int idx = tid; idx < 16384; idx += 128) {
            int b = idx >> 7, i = idx & 127;
            float v = (i < 121) ? xc[(size_t)b * (C_*HW_) + i] : 0.0f;
            uint32_t off = 32768u + (uint32_t)b*256 + ((((uint32_t)i >> 3) ^ (b & 7)) << 4) + (i & 7)*2;
            *reinterpret_cast<__nv_bfloat16*>(base + off) = __float2bfloat16_rn(v);
        }
    }
    __syncthreads();

    // --- mma: warp tile 64(m=b) x 32(n=o); 8 k-steps of 16 ---
    int wm = (wid & 1) * 64, wn = (wid >> 1) * 32;
    float acc[4][4][4];
    #pragma unroll
    for (int mi = 0; mi < 4; mi++)
        #pragma unroll
        for (int ni = 0; ni < 4; ni++)
            #pragma unroll
            for (int e = 0; e < 4; e++) acc[mi][ni][e] = 0.0f;

    int a_row = ((lane >> 3) & 1) * 8 + (lane & 7);   // + wm + mi*16
    int a_kc  = (lane >> 4);                          // + k2*2
    int b_row = ((lane >> 4) << 3) + (lane & 7);      // + wn + np*16
    int b_kc  = ((lane >> 3) & 1);                    // + k2*2

    #pragma unroll 1
    for (int k2 = 0; k2 < 8; k2++) {
        uint32_t af[4][4], bf[2][4];
        #pragma unroll
        for (int mi = 0; mi < 4; mi++) {
            int row = wm + mi*16 + a_row;
            uint32_t addr = Xb + (uint32_t)row*256 + (((uint32_t)(k2*2 + a_kc) ^ (row & 7)) << 4);
            ldsm4(af[mi], addr);
        }
        #pragma unroll
        for (int np = 0; np < 2; np++) {
            int row = wn + np*16 + b_row;
            uint32_t addr = Tb + (uint32_t)row*256 + (((uint32_t)(k2*2 + b_kc) ^ (row & 7)) << 4);
            ldsm4(bf[np], addr);
        }
        #pragma unroll
        for (int mi = 0; mi < 4; mi++)
            #pragma unroll
            for (int ni = 0; ni < 4; ni++)
                mma16816(acc[mi][ni], af[mi],
                         bf[ni >> 1][(ni & 1) * 2], bf[ni >> 1][(ni & 1) * 2 + 1]);
    }
    __syncthreads();

    // --- stage D as bf16, pitch 264B (bank-spread), then coalesced copy-out ---
    {
        int r0 = lane >> 2, c0 = (lane & 3) * 2;
        #pragma unroll
        for (int mi = 0; mi < 4; mi++) {
            int brow = wm + mi*16 + r0;
            #pragma unroll
            for (int ni = 0; ni < 4; ni++) {
                int ocol = wn + ni*8 + c0;
                *reinterpret_cast<__nv_bfloat162*>(base + (size_t)brow*264 + ocol*2) =
                    __floats2bfloat162_rn(acc[mi][ni][0], acc[mi][ni][1]);
                *reinterpret_cast<__nv_bfloat162*>(base + (size_t)(brow+8)*264 + ocol*2) =
                    __floats2bfloat162_rn(acc[mi][ni][2], acc[mi][ni][3]);
            }
        }
    }
    __syncthreads();
    __nv_bfloat16* dst = g_xfb + (size_t)c * M_;
    for (int idx = tid; idx < M_; idx += 256) {
        int b = idx / 121, o = idx - b * 121;
        dst[idx] = *reinterpret_cast<__nv_bfloat16*>(base + (size_t)b*264 + o*2);
    }
}

// K2c: W fp32 -> bf16 (layout preserved, k contiguous).
__global__ __launch_bounds__(256)
void convert_w(const float4* __restrict__ w) {
    int i = blockIdx.x * 256 + threadIdx.x;
    float4 v = w[i];
    __nv_bfloat162* d2 = reinterpret_cast<__nv_bfloat162*>(g_wb);
    d2[2*i]   = __floats2bfloat162_rn(v.x, v.y);
    d2[2*i+1] = __floats2bfloat162_rn(v.z, v.w);
}

// ---------------------------------------------------------------------------
// K3: bf16 mma.sync GEMM, CTA tile 128(M) x 256(N), 8 warps x (64x64),
// K-tile 64, 3-stage cp.async pipeline, 1 CTA/SM (145KB smem).
// A col-major [k][m] staged into 256B-row swizzle, ldmatrix.trans.
// B row-major [n][k], SW128 128B rows. Fused BN/ReLU/gate/residual.
// ---------------------------------------------------------------------------
#define KT_    64
#define NKT_   (C_/KT_)          /* 32 */
#define ASTG   16384             /* 64 k-rows x 256B */
#define BSTG   32768             /* 256 n-rows x 128B */
#define STGSZ  (ASTG+BSTG)
#define NT_    256
#define SW(o)  ((o) ^ (((o) >> 3) & 0x70))

__global__ __launch_bounds__(256, 1)
void gemm_tc(const float* __restrict__ x,
             const float* __restrict__ cb, const float* __restrict__ ga,
             const float* __restrict__ be, const float* __restrict__ me,
             const float* __restrict__ va, const float* __restrict__ gate,
             float* __restrict__ out) {
    extern __shared__ char smc[];
    uint32_t sb    = smem_addr_u32(smc);
    uint32_t tiles = (sb + 1023) & ~1023u;

    int tid = threadIdx.x, wid = tid >> 5, lane = tid & 31;
    int bx = blockIdx.x, by = blockIdx.y;
    int wm = (wid & 1) * 64;                 // 2 m-warps x 4 n-warps
    int wn = (wid >> 1) * 64;

    const __nv_bfloat16* Ag = g_xfb + bx * 128;              // (k,m) at k*M_ + m
    const __nv_bfloat16* Bg = g_wb  + (size_t)(by * NT_) * C_;

    auto load_stage = [&](int kt, int buf) {
        const __nv_bfloat16* as = Ag + (size_t)(kt * KT_) * M_;
        const __nv_bfloat16* bs = Bg + kt * KT_;
        uint32_t Ab = tiles + buf * STGSZ, Bb = Ab + ASTG;
        #pragma unroll
        for (int q = 0; q < 4; q++) {               // A: 64 k-rows x 16 chunks of 16B
            int idx = tid + q * 256;
            int row = idx >> 4, ch = idx & 15;
            cpa16(Ab + (uint32_t)row*256 + (((uint32_t)ch ^ (row & 7)) << 4),
                  as + (size_t)row * M_ + ch * 8);
        }
        #pragma unroll
        for (int q = 0; q < 8; q++) {               // B: 256 n-rows x 8 chunks of 16B
            int idx = tid + q * 256;
            int row = idx >> 3, ch = idx & 7;
            uint32_t off = row * 128 + ch * 16;
            cpa16(Bb + SW(off), bs + (size_t)row * C_ + ch * 8);
        }
    };

    float acc[4][8][4];
    #pragma unroll
    for (int mi = 0; mi < 4; mi++)
        #pragma unroll
        for (int ni = 0; ni < 8; ni++)
            #pragma unroll
            for (int e = 0; e < 4; e++) acc[mi][ni][e] = 0.0f;

    // A (trans): slot s=lane>>3: m_half=s&1, k_half=s>>1.
    int at_k  = ((lane >> 4) & 1) * 8 + (lane & 7);   // + ks*16  (k-row)
    int at_mh = ((lane >> 3) & 1) * 8;                // + wm + mi*16 (m elems)
    // B (non-trans), 128B rows:
    int b_row  = wn + ((lane >> 4) << 3) + (lane & 7);
    int b_colb = ((lane >> 3) & 1) * 16;

    load_stage(0, 0);
    asm volatile("cp.async.commit_group;" ::: "memory");
    load_stage(1, 1);
    asm volatile("cp.async.commit_group;" ::: "memory");

    int buf = 0, nbuf = 2;
    #pragma unroll 1
    for (int t = 0; t < NKT_; t++) {
        asm volatile("cp.async.wait_group 1;" ::: "memory");   // stage t landed
        __syncthreads();

        if (t + 2 < NKT_) load_stage(t + 2, nbuf);
        asm volatile("cp.async.commit_group;" ::: "memory");

        uint32_t Ab = tiles + buf * STGSZ, Bb = Ab + ASTG;
        #pragma unroll
        for (int ks = 0; ks < 4; ks++) {
            uint32_t af[4][4], bf[4][4];
            int krow = ks * 16 + at_k;
            #pragma unroll
            for (int mi = 0; mi < 4; mi++) {
                int me = wm + mi*16 + at_mh;
                uint32_t addr = Ab + (uint32_t)krow*256 + ((((uint32_t)me >> 3) ^ (krow & 7)) << 4);
                ldsm4t(af[mi], addr);
            }
            #pragma unroll
            for (int np = 0; np < 4; np++) {
                uint32_t off = (uint32_t)(b_row + np*16) * 128 + ks*32 + b_colb;
                ldsm4(bf[np], Bb + SW(off));
            }
            #pragma unroll
            for (int mi = 0; mi < 4; mi++)
                #pragma unroll
                for (int ni = 0; ni < 8; ni++)
                    mma16816(acc[mi][ni], af[mi],
                             bf[ni >> 1][(ni & 1) * 2], bf[ni >> 1][(ni & 1) * 2 + 1]);
        }
        buf  = (buf  == 2) ? 0 : buf  + 1;
        nbuf = (nbuf == 2) ? 0 : nbuf + 1;
    }

    // Epilogue: smem col-major (pitch 132, 256 cols) + BN/ReLU/gate/residual.
    float* Ep   = reinterpret_cast<float*>(smc + (tiles - sb));
    float* s_sc = Ep + 132 * NT_;
    float* s_bi = s_sc + NT_;
    __syncthreads();
    {
        int r0 = lane >> 2, c0 = (lane & 3) * 2;
        #pragma unroll
        for (int mi = 0; mi < 4; mi++) {
            int mrow = wm + mi * 16 + r0;
            #pragma unroll
            for (int ni = 0; ni < 8; ni++) {
                int ncol = wn + ni * 8 + c0;
                Ep[(mrow)     + (ncol)     * 132] = acc[mi][ni][0];
                Ep[(mrow)     + (ncol + 1) * 132] = acc[mi][ni][1];
                Ep[(mrow + 8) + (ncol)     * 132] = acc[mi][ni][2];
                Ep[(mrow + 8) + (ncol + 1) * 132] = acc[mi][ni][3];
            }
        }
    }
    {
        int o = by * NT_ + tid;
        float sc = ga[o] * rsqrtf(va[o] + 1e-5f);
        s_sc[tid] = sc;
        s_bi[tid] = (cb[o] - me[o]) * sc + be[o];
    }
    __syncthreads();

    float g = fminf(fmaxf(gate[0], 0.0f), 1.0f);
    #pragma unroll 4
    for (int q = 0; q < 128; q++) {
        int idx = tid + q * 256;
        int nn = idx >> 7, mm = idx & 127;
        float v = Ep[mm + nn * 132];
        v = fmaxf(v * s_sc[nn] + s_bi[nn], 0.0f);
        int m = bx * 128 + mm;
        int b = m / 121, hw = m - b * 121;
        size_t oi = (size_t)b * (C_*HW_) + (size_t)(by * NT_ + nn) * HW_ + hw;
        out[oi] = x[oi] + g * v;
    }
}

// ---------------------------------------------------------------------------
extern "C" void kernel_launch(void* const* d_in, const int* in_sizes, int n_in,
                              void* d_out, int out_size) {
    const float* x    = (const float*)d_in[0];
    const float* ft   = (const float*)d_in[1];
    const float* gate = (const float*)d_in[2];
    const float* w    = (const float*)d_in[3];
    const float* cbias= (const float*)d_in[4];
    const float* ga   = (const float*)d_in[5];
    const float* be   = (const float*)d_in[6];
    const float* me   = (const float*)d_in[7];
    const float* va   = (const float*)d_in[8];
    float* out = (float*)d_out;

    size_t smemF = 2048 + 2 * 32768;                 // hdr + T + X
    cudaFuncSetAttribute(filter_mma2, cudaFuncAttributeMaxDynamicSharedMemorySize, (int)smemF);
    filter_mma2<<<C_, 256, smemF>>>(x, ft);

    convert_w<<<(C_*C_/4)/256, 256>>>((const float4*)w);

    size_t stages = 1024 + 3 * STGSZ;                          // ~145 KB
    size_t epi    = 1024 + (132*NT_ + 2*NT_) * sizeof(float);  // ~136 KB
    size_t smem3  = stages > epi ? stages : epi;
    cudaFuncSetAttribute(gemm_tc, cudaFuncAttributeMaxDynamicSharedMemorySize, (int)smem3);
    gemm_tc<<<dim3(121, C_/NT_), 256, smem3>>>(x, cbias, ga, be, me, va, gate, out);
}